// round 13
// baseline (speedup 1.0000x reference)
#include <cuda_runtime.h>

#define BS    64
#define NC    80
#define NA    8400
#define TOPK  13
#define EPSF  1e-9f

#define NTH    512
#define GRID   (BS * 2)            // 128 blocks, single wave (<=148 SMs)
#define HCHNK  (NA / 8)            // 1050 float4 chunks per half-row
#define ELEM4  3                   // ceil(1050 / 512)
#define NWARP  (NTH / 32)          // 16
#define CAP    256                 // survivor buffer capacity

#define PB_ANCH 66                 // phase-B anchors per block: 128*66 >= 8400

// norm_align_metric scratch (float bits). Zeroed at load; phase B resets its
// own slice after reading, so it's zeroed again before every next call.
__device__ unsigned int d_norm_bits[NA];
// Per-half-row sorted top-13 lists, packed u64: (sval<<32)|(~anchor). Pad 16.
__device__ unsigned long long d_halftop[GRID * 16];
// Monotone ticket counters for the two single-wave grid syncs (never reset).
__device__ unsigned int d_arrive1;
__device__ unsigned int d_arrive2;

static __device__ __forceinline__ void grid_sync(unsigned int* ctr, int tid) {
    __syncthreads();
    if (tid == 0) {
        __threadfence();
        unsigned old = atomicAdd(ctr, 1u);
        unsigned tgt = (old & ~(unsigned)(GRID - 1)) + GRID;
        while (*(volatile unsigned*)ctr < tgt) { }
        __threadfence();
    }
    __syncthreads();
}

// 128 blocks: block bid = row (bid>>1), half (bid&1). 512 threads, one wave.
// Candidate encoding: sval = float_bits(align) + 1 (u32, monotone for
// align>=0; 0 = consumed/OOB). top_k tie order = (max val, min anchor).
__global__ __launch_bounds__(NTH, 1) void taa_fused(
    const float* __restrict__ pd_scores,   // (BS, NC, NA)
    const float* __restrict__ pd_bboxes,   // (BS, 4, NA)
    const int*   __restrict__ gt_labels,   // (BS,)
    const float* __restrict__ gt_bboxes,   // (BS, 4)
    float*       __restrict__ target_out,  // (NA, BS)
    float*       __restrict__ mask_out)    // (BS, NA)
{
    __shared__ unsigned s_wmax[NWARP];
    __shared__ unsigned s_cnt;
    __shared__ unsigned s_L;
    __shared__ unsigned s_bufv[CAP];
    __shared__ unsigned s_bufi[CAP];
    __shared__ unsigned s_candv[TOPK * NWARP];   // fallback only
    __shared__ unsigned s_candi[TOPK * NWARP];   // fallback only
    __shared__ float s_topv[TOPK];
    __shared__ int   s_topi[TOPK];
    __shared__ float s_iou[TOPK];
    __shared__ float s_ratio;
    __shared__ float s_lab[BS];

    const int bid  = blockIdx.x;
    const int b    = bid >> 1;
    const int h    = bid & 1;
    const int tid  = threadIdx.x;
    const int lane = tid & 31;
    const int wid  = tid >> 5;

    if (tid < BS) s_lab[tid] = (float)gt_labels[tid];
    if (tid == 0) s_cnt = 0u;

    const float gx1 = gt_bboxes[b * 4 + 0];
    const float gy1 = gt_bboxes[b * 4 + 1];
    const float gx2 = gt_bboxes[b * 4 + 2];
    const float gy2 = gt_bboxes[b * 4 + 3];
    const float area1 = fmaxf(gx2 - gx1, 0.f) * fmaxf(gy2 - gy1, 0.f);
    const int   label = gt_labels[b];

    const float4* __restrict__ px1 = (const float4*)(pd_bboxes + ((long)b * 4 + 0) * NA);
    const float4* __restrict__ py1 = (const float4*)(pd_bboxes + ((long)b * 4 + 1) * NA);
    const float4* __restrict__ px2 = (const float4*)(pd_bboxes + ((long)b * 4 + 2) * NA);
    const float4* __restrict__ py2 = (const float4*)(pd_bboxes + ((long)b * 4 + 3) * NA);
    const float4* __restrict__ sc  = (const float4*)(pd_scores + ((long)b * NC + label) * NA);
    float* __restrict__ mrow = mask_out + (long)b * NA;
    float4* __restrict__ mrow4 = (float4*)mrow;

    // ---- Phase A.1: align metric over this half (chunks [h*1050, +1050)).
    const int cbase = h * HCHNK;
    unsigned sval[ELEM4 * 4];
    #pragma unroll
    for (int i = 0; i < ELEM4; i++) {
        int cl = i * NTH + tid;
        if (cl < HCHNK) {
            int c = cbase + cl;
            float4 vx1 = px1[c], vy1 = py1[c], vx2 = px2[c], vy2 = py2[c];
            float4 vsc = sc[c];
            #pragma unroll
            for (int j = 0; j < 4; j++) {
                float bx1 = (&vx1.x)[j], by1 = (&vy1.x)[j];
                float bx2 = (&vx2.x)[j], by2 = (&vy2.x)[j];
                float iw = fmaxf(fminf(gx2, bx2) - fmaxf(gx1, bx1), 0.f);
                float ih = fmaxf(fminf(gy2, by2) - fmaxf(gy1, by1), 0.f);
                float ov = iw * ih;
                float a2 = fmaxf(bx2 - bx1, 0.f) * fmaxf(by2 - by1, 0.f);
                float iou = __fdividef(ov, area1 + a2 - ov + EPSF);
                float iou2 = iou * iou;
                float align = (&vsc.x)[j] * (iou2 * iou2 * iou2);
                sval[i * 4 + j] = __float_as_uint(align) + 1u;
            }
            mrow4[c] = make_float4(0.f, 0.f, 0.f, 0.f);
        } else {
            #pragma unroll
            for (int j = 0; j < 4; j++) sval[i * 4 + j] = 0u;
        }
    }
    // Global anchor for element (i,j): ((cbase + i*NTH + tid) << 2) + j.
    #define ANCH(i, j) ((unsigned)(((cbase + (i) * NTH + tid) << 2) + (j)))

    // ---- Per-warp max -> L = 13th largest of the 16 warp maxima (valid
    //      lower bound on this half's 13th-largest value).
    unsigned bv = 0u;
    #pragma unroll
    for (int e = 0; e < ELEM4 * 4; e++) bv = (sval[e] > bv) ? sval[e] : bv;
    unsigned wmv = __reduce_max_sync(0xFFFFFFFFu, bv);
    if (lane == 0) s_wmax[wid] = wmv;
    __syncthreads();

    if (wid == 0) {
        unsigned v = (lane < NWARP) ? s_wmax[lane] : 0u;
        unsigned Lv = 0u;
        #pragma unroll
        for (int k = 0; k < TOPK; k++) {
            unsigned mv = __reduce_max_sync(0xFFFFFFFFu, v);
            unsigned ml = __reduce_min_sync(0xFFFFFFFFu,
                                            (v == mv) ? (unsigned)lane : 0xFFFFFFFFu);
            if ((unsigned)lane == ml) v = 0u;
            Lv = mv;
        }
        if (lane == 0) s_L = Lv;
    }
    __syncthreads();

    // ---- Filter & compact survivors (sval >= L).
    {
        const unsigned L = s_L;
        #pragma unroll
        for (int i = 0; i < ELEM4; i++) {
            #pragma unroll
            for (int j = 0; j < 4; j++) {
                if (sval[i * 4 + j] >= L) {
                    unsigned pos = atomicAdd(&s_cnt, 1u);
                    if (pos < CAP) {
                        s_bufv[pos] = sval[i * 4 + j];
                        s_bufi[pos] = ANCH(i, j);
                    }
                }
            }
        }
    }
    __syncthreads();

    const unsigned ncand = s_cnt;
    if (ncand <= CAP) {
        // ---- Fast path: warp 0 selects exact half top-13 from survivors.
        if (wid == 0) {
            const int nper = (int)((ncand + 31u) >> 5);
            for (int k = 0; k < TOPK; k++) {
                unsigned bv2 = 0u, ba2 = 0xFFFFFFFFu;
                int bslot = 0;
                for (int j = 0; j < nper; j++) {
                    int p = lane + (j << 5);
                    if (p < (int)ncand) {
                        unsigned v = s_bufv[p], a = s_bufi[p];
                        if (v > bv2 || (v == bv2 && a < ba2)) { bv2 = v; ba2 = a; bslot = p; }
                    }
                }
                unsigned mv = __reduce_max_sync(0xFFFFFFFFu, bv2);
                unsigned mi = __reduce_min_sync(0xFFFFFFFFu,
                                                (bv2 == mv) ? ba2 : 0xFFFFFFFFu);
                if (lane == 0)
                    d_halftop[bid * 16 + k] =
                        ((unsigned long long)mv << 32) |
                        (unsigned long long)(0xFFFFFFFFu - mi);
                if (bv2 == mv && ba2 == mi) s_bufv[bslot] = 0u;
            }
        }
    } else {
        // ---- Fallback (exact): per-warp 13 rounds + warp-0 merge.
        #pragma unroll
        for (int k = 0; k < TOPK; k++) {
            unsigned fv = 0u, fa = 0xFFFFFFFFu;
            #pragma unroll
            for (int i = 0; i < ELEM4; i++) {
                #pragma unroll
                for (int j = 0; j < 4; j++)
                    if (sval[i * 4 + j] > fv) { fv = sval[i * 4 + j]; fa = ANCH(i, j); }
            }
            unsigned mv = __reduce_max_sync(0xFFFFFFFFu, fv);
            unsigned mi = __reduce_min_sync(0xFFFFFFFFu, (fv == mv) ? fa : 0xFFFFFFFFu);
            if (lane == 0) { s_candv[k * NWARP + wid] = mv; s_candi[k * NWARP + wid] = mi; }
            #pragma unroll
            for (int i = 0; i < ELEM4; i++) {
                #pragma unroll
                for (int j = 0; j < 4; j++)
                    if (ANCH(i, j) == mi) sval[i * 4 + j] = 0u;
            }
        }
        __syncthreads();
        if (wid == 0) {
            unsigned qv[TOPK], qi[TOPK];
            #pragma unroll
            for (int j = 0; j < TOPK; j++) {
                qv[j] = (lane < NWARP) ? s_candv[j * NWARP + lane] : 0u;
                qi[j] = (lane < NWARP) ? s_candi[j * NWARP + lane] : 0xFFFFFFFFu;
            }
            #pragma unroll
            for (int k = 0; k < TOPK; k++) {
                unsigned fv = 0u, fa = 0xFFFFFFFFu;
                #pragma unroll
                for (int j = 0; j < TOPK; j++)
                    if (qv[j] > fv) { fv = qv[j]; fa = qi[j]; }
                unsigned mv = __reduce_max_sync(0xFFFFFFFFu, fv);
                unsigned mi = __reduce_min_sync(0xFFFFFFFFu, (fv == mv) ? fa : 0xFFFFFFFFu);
                if (lane == 0)
                    d_halftop[bid * 16 + k] =
                        ((unsigned long long)mv << 32) |
                        (unsigned long long)(0xFFFFFFFFu - mi);
                #pragma unroll
                for (int j = 0; j < TOPK; j++)
                    if (qi[j] == mi) qv[j] = 0u;
            }
        }
    }
    #undef ANCH

    // ---- Grid sync #1: all half-lists visible.
    grid_sync(&d_arrive1, tid);

    // ---- Even blocks: merge the two sorted 13-lists -> exact row top-13.
    if (h == 0) {
        if (wid == 0) {
            unsigned cv = 0u, ci = 0xFFFFFFFFu;
            if (lane < TOPK) {
                unsigned long long w = d_halftop[(2 * b) * 16 + lane];
                cv = (unsigned)(w >> 32);
                ci = 0xFFFFFFFFu - (unsigned)(w & 0xFFFFFFFFull);
            } else if (lane < 2 * TOPK) {
                unsigned long long w = d_halftop[(2 * b + 1) * 16 + (lane - TOPK)];
                cv = (unsigned)(w >> 32);
                ci = 0xFFFFFFFFu - (unsigned)(w & 0xFFFFFFFFull);
            }
            #pragma unroll
            for (int k = 0; k < TOPK; k++) {
                unsigned mv = __reduce_max_sync(0xFFFFFFFFu, cv);
                unsigned mi = __reduce_min_sync(0xFFFFFFFFu,
                                                (cv == mv) ? ci : 0xFFFFFFFFu);
                if (lane == 0) {
                    s_topv[k] = __uint_as_float(mv - 1u);
                    s_topi[k] = (int)mi;
                }
                if (cv == mv && ci == mi) cv = 0u;   // consume (anchors unique)
            }
        }
        __syncthreads();

        // IoU recompute at winners (pos_overlaps).
        if (tid < TOPK) {
            int a = s_topi[tid];
            const float* pb = pd_bboxes + (long)b * 4 * NA;
            float bx1 = pb[a], by1 = pb[NA + a], bx2 = pb[2 * NA + a], by2 = pb[3 * NA + a];
            float iw = fmaxf(fminf(gx2, bx2) - fmaxf(gx1, bx1), 0.f);
            float ih = fmaxf(fminf(gy2, by2) - fmaxf(gy1, by1), 0.f);
            float ov = iw * ih;
            float a2 = fmaxf(bx2 - bx1, 0.f) * fmaxf(by2 - by1, 0.f);
            s_iou[tid] = __fdividef(ov, area1 + a2 - ov + EPSF);
        }
        __syncthreads();

        if (tid == 0) {
            float po = 0.f;
            #pragma unroll
            for (int k = 0; k < TOPK; k++) po = fmaxf(po, s_iou[k]);
            s_ratio = po / (s_topv[0] + EPSF);
        }
        __syncthreads();

        if (s_topv[0] > EPSF && tid < TOPK) {
            int a = s_topi[tid];
            mrow[a] = 1.0f;
            float contrib = s_topv[tid] * s_ratio;
            atomicMax(&d_norm_bits[a], __float_as_uint(contrib));
        }
        // invalid row: mask all-zero (cnt>1 collapse), no norm contribution.
    }

    // ---- Grid sync #2: all norm contributions visible.
    grid_sync(&d_arrive2, tid);

    // ---- Phase B: target_scores[a, j] = lab[j] * norm[a], (NA, BS) layout.
    const int a0 = bid * PB_ANCH;
    const int nA = (a0 + PB_ANCH <= NA) ? PB_ANCH : (NA - a0);
    const int la = tid >> 4;            // 0..31 anchors per sweep
    const int j4 = (tid & 15) << 2;     // column group of 4

    #pragma unroll
    for (int it = 0; it < 3; it++) {    // 3*32 = 96 >= 66
        int al = it * 32 + la;
        if (al < nA) {
            int a = a0 + al;
            float nv = __uint_as_float(d_norm_bits[a]);
            float4 v = make_float4(nv * s_lab[j4 + 0], nv * s_lab[j4 + 1],
                                   nv * s_lab[j4 + 2], nv * s_lab[j4 + 3]);
            *reinterpret_cast<float4*>(target_out + (long)a * BS + j4) = v;
        }
    }
    __syncthreads();
    if (tid < nA) d_norm_bits[a0 + tid] = 0u;   // reset own slice for next call
}

extern "C" void kernel_launch(void* const* d_in, const int* in_sizes, int n_in,
                              void* d_out, int out_size) {
    const float* pd_scores = (const float*)d_in[0];
    const float* pd_bboxes = (const float*)d_in[1];
    const int*   gt_labels = (const int*)d_in[2];
    const float* gt_bboxes = (const float*)d_in[3];

    float* target = (float*)d_out;                       // (NA, BS)
    float* mask   = (float*)d_out + (size_t)NA * BS;     // (BS, NA)

    taa_fused<<<GRID, NTH>>>(pd_scores, pd_bboxes, gt_labels, gt_bboxes,
                             target, mask);
}

// round 14
// speedup vs baseline: 1.3608x; 1.3608x over previous
#include <cuda_runtime.h>

#define BS    64
#define NC    80
#define NA    8400
#define TOPK  13
#define EPSF  1e-9f

#define NTH    512
#define NCHNK  (NA / 4)            // 2100 float4 chunks (exact)
#define ELEM4  5                   // ceil(2100 / 512)
#define NWARP  (NTH / 32)          // 16
#define CAP    256                 // survivor buffer capacity (rank path)

#define PB_ANCH 132                // phase-B anchors per block: 64*132 >= 8400

// Per-row top-13 (contrib_bits<<32 | anchor), padded to 16. Entries 0..12 are
// fully rewritten every call; 13..15 stay zero (anchor 0, contrib 0 -> no-op).
__device__ unsigned long long d_rowtop[BS * 16];
// Monotone ticket counter for the single-wave grid sync (never reset).
__device__ unsigned int d_arrive;

static __device__ __forceinline__ void grid_sync(unsigned int* ctr, int tid) {
    __syncthreads();
    if (tid == 0) {
        __threadfence();
        unsigned old = atomicAdd(ctr, 1u);
        unsigned tgt = (old & ~(unsigned)(BS - 1)) + BS;
        while (*(volatile unsigned*)ctr < tgt) { }
        __threadfence();
    }
    __syncthreads();
}

// 64 blocks (one per batch row), 512 threads, single wave, ONE grid sync.
// Candidate encoding: sval = float_bits(align) + 1 (u32, monotone for
// align>=0; 0 = OOB sentinel). top_k tie order = (max val, min anchor).
__global__ __launch_bounds__(NTH, 1) void taa_fused(
    const float* __restrict__ pd_scores,   // (BS, NC, NA)
    const float* __restrict__ pd_bboxes,   // (BS, 4, NA)
    const int*   __restrict__ gt_labels,   // (BS,)
    const float* __restrict__ gt_bboxes,   // (BS, 4)
    float*       __restrict__ target_out,  // (NA, BS)
    float*       __restrict__ mask_out)    // (BS, NA)
{
    __shared__ unsigned s_wmax[NWARP];
    __shared__ unsigned s_cnt;
    __shared__ unsigned s_L;
    __shared__ unsigned s_bufv[CAP];
    __shared__ unsigned s_bufi[CAP];
    __shared__ float    s_bufo[CAP];             // iou of each survivor
    __shared__ unsigned s_candv[TOPK * NWARP];   // fallback only
    __shared__ unsigned s_candi[TOPK * NWARP];   // fallback only
    __shared__ float s_topv[TOPK];
    __shared__ int   s_topi[TOPK];
    __shared__ float s_iou[TOPK];
    __shared__ float s_ratio;
    __shared__ float s_lab[BS];
    __shared__ unsigned s_norm[PB_ANCH];         // phase-B norm (float bits)

    const int b    = blockIdx.x;
    const int tid  = threadIdx.x;
    const int lane = tid & 31;
    const int wid  = tid >> 5;

    if (tid < BS) s_lab[tid] = (float)gt_labels[tid];
    if (tid == 0) s_cnt = 0u;

    const float gx1 = gt_bboxes[b * 4 + 0];
    const float gy1 = gt_bboxes[b * 4 + 1];
    const float gx2 = gt_bboxes[b * 4 + 2];
    const float gy2 = gt_bboxes[b * 4 + 3];
    const float area1 = fmaxf(gx2 - gx1, 0.f) * fmaxf(gy2 - gy1, 0.f);
    const int   label = gt_labels[b];

    const float4* __restrict__ px1 = (const float4*)(pd_bboxes + ((long)b * 4 + 0) * NA);
    const float4* __restrict__ py1 = (const float4*)(pd_bboxes + ((long)b * 4 + 1) * NA);
    const float4* __restrict__ px2 = (const float4*)(pd_bboxes + ((long)b * 4 + 2) * NA);
    const float4* __restrict__ py2 = (const float4*)(pd_bboxes + ((long)b * 4 + 3) * NA);
    const float4* __restrict__ sc  = (const float4*)(pd_scores + ((long)b * NC + label) * NA);
    float* __restrict__ mrow = mask_out + (long)b * NA;
    float4* __restrict__ mrow4 = (float4*)mrow;

    // ---- Phase A.1: align metric + iou -> registers; zero mask row.
    unsigned sval[ELEM4 * 4];
    float    fiou[ELEM4 * 4];
    #pragma unroll
    for (int i = 0; i < ELEM4; i++) {
        int c = i * NTH + tid;
        if (c < NCHNK) {
            float4 vx1 = px1[c], vy1 = py1[c], vx2 = px2[c], vy2 = py2[c];
            float4 vsc = sc[c];
            #pragma unroll
            for (int j = 0; j < 4; j++) {
                float bx1 = (&vx1.x)[j], by1 = (&vy1.x)[j];
                float bx2 = (&vx2.x)[j], by2 = (&vy2.x)[j];
                float iw = fmaxf(fminf(gx2, bx2) - fmaxf(gx1, bx1), 0.f);
                float ih = fmaxf(fminf(gy2, by2) - fmaxf(gy1, by1), 0.f);
                float ov = iw * ih;
                float a2 = fmaxf(bx2 - bx1, 0.f) * fmaxf(by2 - by1, 0.f);
                float iou = __fdividef(ov, area1 + a2 - ov + EPSF);
                float iou2 = iou * iou;
                float align = (&vsc.x)[j] * (iou2 * iou2 * iou2);
                sval[i * 4 + j] = __float_as_uint(align) + 1u;
                fiou[i * 4 + j] = iou;
            }
            mrow4[c] = make_float4(0.f, 0.f, 0.f, 0.f);
        } else {
            #pragma unroll
            for (int j = 0; j < 4; j++) { sval[i * 4 + j] = 0u; fiou[i * 4 + j] = 0.f; }
        }
    }
    #define ANCH(i, j) ((unsigned)(((i * NTH + tid) << 2) + (j)))

    // ---- Warp maxima -> L = 13th largest of the 16 (rank-based, 1 pass).
    unsigned bv = 0u;
    #pragma unroll
    for (int e = 0; e < ELEM4 * 4; e++) bv = (sval[e] > bv) ? sval[e] : bv;
    unsigned wmv = __reduce_max_sync(0xFFFFFFFFu, bv);
    if (lane == 0) s_wmax[wid] = wmv;
    __syncthreads();

    if (wid == 0) {
        unsigned v = (lane < NWARP) ? s_wmax[lane] : 0u;
        int rank = 0;
        #pragma unroll
        for (int p = 0; p < NWARP; p++) {
            unsigned v2 = s_wmax[p];
            rank += (v2 > v) || (v2 == v && p < lane);   // lex (v desc, lane asc)
        }
        if (lane < NWARP && rank == TOPK - 1) s_L = v;   // unique rank 12
    }
    __syncthreads();

    // ---- Filter & compact survivors (sval >= L); keep iou alongside.
    {
        const unsigned L = s_L;
        #pragma unroll
        for (int i = 0; i < ELEM4; i++) {
            #pragma unroll
            for (int j = 0; j < 4; j++) {
                if (sval[i * 4 + j] >= L) {
                    unsigned pos = atomicAdd(&s_cnt, 1u);
                    if (pos < CAP) {
                        s_bufv[pos] = sval[i * 4 + j];
                        s_bufi[pos] = ANCH(i, j);
                        s_bufo[pos] = fiou[i * 4 + j];
                    }
                }
            }
        }
    }
    __syncthreads();

    const unsigned ncand = s_cnt;
    if (ncand <= CAP) {
        // ---- Fast path: parallel rank selection (order-independent, exact).
        if (tid < (int)ncand) {
            unsigned v = s_bufv[tid], a = s_bufi[tid];
            int rank = 0;
            for (int p = 0; p < (int)ncand; p++) {
                unsigned v2 = s_bufv[p], a2 = s_bufi[p];
                rank += (v2 > v) || (v2 == v && a2 < a);
            }
            if (rank < TOPK) {
                s_topv[rank] = __uint_as_float(v - 1u);
                s_topi[rank] = (int)a;
                s_iou[rank]  = s_bufo[tid];
            }
        }
        __syncthreads();
    } else {
        // ---- Fallback (exact, tie-storm safe): per-warp rounds + merge.
        #pragma unroll
        for (int k = 0; k < TOPK; k++) {
            unsigned fv = 0u, fa = 0xFFFFFFFFu;
            #pragma unroll
            for (int i = 0; i < ELEM4; i++) {
                #pragma unroll
                for (int j = 0; j < 4; j++)
                    if (sval[i * 4 + j] > fv) { fv = sval[i * 4 + j]; fa = ANCH(i, j); }
            }
            unsigned mv = __reduce_max_sync(0xFFFFFFFFu, fv);
            unsigned mi = __reduce_min_sync(0xFFFFFFFFu, (fv == mv) ? fa : 0xFFFFFFFFu);
            if (lane == 0) { s_candv[k * NWARP + wid] = mv; s_candi[k * NWARP + wid] = mi; }
            #pragma unroll
            for (int i = 0; i < ELEM4; i++) {
                #pragma unroll
                for (int j = 0; j < 4; j++)
                    if (ANCH(i, j) == mi) sval[i * 4 + j] = 0u;
            }
        }
        __syncthreads();
        if (wid == 0) {
            unsigned qv[TOPK], qi[TOPK];
            #pragma unroll
            for (int j = 0; j < TOPK; j++) {
                qv[j] = (lane < NWARP) ? s_candv[j * NWARP + lane] : 0u;
                qi[j] = (lane < NWARP) ? s_candi[j * NWARP + lane] : 0xFFFFFFFFu;
            }
            #pragma unroll
            for (int k = 0; k < TOPK; k++) {
                unsigned fv = 0u, fa = 0xFFFFFFFFu;
                #pragma unroll
                for (int j = 0; j < TOPK; j++)
                    if (qv[j] > fv) { fv = qv[j]; fa = qi[j]; }
                unsigned mv = __reduce_max_sync(0xFFFFFFFFu, fv);
                unsigned mi = __reduce_min_sync(0xFFFFFFFFu, (fv == mv) ? fa : 0xFFFFFFFFu);
                if (lane == 0) { s_topv[k] = __uint_as_float(mv - 1u); s_topi[k] = (int)mi; }
                #pragma unroll
                for (int j = 0; j < TOPK; j++)
                    if (qi[j] == mi) qv[j] = 0u;
            }
        }
        __syncthreads();
        // Recompute iou at winners (fallback only).
        if (tid < TOPK) {
            int a = s_topi[tid];
            const float* pb = pd_bboxes + (long)b * 4 * NA;
            float bx1 = pb[a], by1 = pb[NA + a], bx2 = pb[2 * NA + a], by2 = pb[3 * NA + a];
            float iw = fmaxf(fminf(gx2, bx2) - fmaxf(gx1, bx1), 0.f);
            float ih = fmaxf(fminf(gy2, by2) - fmaxf(gy1, by1), 0.f);
            float ov = iw * ih;
            float a2 = fmaxf(bx2 - bx1, 0.f) * fmaxf(by2 - by1, 0.f);
            s_iou[tid] = __fdividef(ov, area1 + a2 - ov + EPSF);
        }
        __syncthreads();
    }
    #undef ANCH

    // ---- Ratio, mask winners, publish (anchor, contrib) to d_rowtop.
    if (tid == 0) {
        float po = 0.f;
        #pragma unroll
        for (int k = 0; k < TOPK; k++) po = fmaxf(po, s_iou[k]);
        s_ratio = po / (s_topv[0] + EPSF);   // pos_overlaps / (pos_align + eps)
    }
    __syncthreads();

    if (tid < TOPK) {
        const bool valid = (s_topv[0] > EPSF);
        int a = s_topi[tid];
        float contrib = valid ? (s_topv[tid] * s_ratio) : 0.0f;
        if (valid) mrow[a] = 1.0f;           // mask winner
        d_rowtop[b * 16 + tid] =
            ((unsigned long long)__float_as_uint(contrib) << 32) | (unsigned)a;
    }
    // invalid row: mask all-zero (cnt>1 collapse), contrib 0 -> no norm effect.

    // ---- ONE grid sync: all rowtop entries + masks visible.
    grid_sync(&d_arrive, tid);

    // ---- Phase B: build norm for this block's 132 anchors in smem from the
    //      1024 rowtop entries (pads are zero -> harmless no-op at anchor 0),
    //      then write target_scores[a, j] = lab[j] * norm[a], (NA, BS) layout.
    const int a0 = b * PB_ANCH;
    const int nA = (a0 + PB_ANCH <= NA) ? PB_ANCH : (NA - a0);

    if (tid < PB_ANCH) s_norm[tid] = 0u;
    __syncthreads();

    #pragma unroll
    for (int e = tid; e < BS * 16; e += NTH) {      // 2 iterations
        unsigned long long w = d_rowtop[e];
        unsigned a = (unsigned)(w & 0xFFFFFFFFull);
        unsigned c = (unsigned)(w >> 32);
        if (a >= (unsigned)a0 && a < (unsigned)(a0 + nA))
            atomicMax(&s_norm[a - a0], c);          // float bits, values >= 0
    }
    __syncthreads();

    const int la = tid >> 4;            // 0..31 anchors per sweep
    const int j4 = (tid & 15) << 2;     // column group of 4
    #pragma unroll
    for (int it = 0; it < 5; it++) {    // 5*32 = 160 >= 132
        int al = it * 32 + la;
        if (al < nA) {
            float nv = __uint_as_float(s_norm[al]);
            float4 v = make_float4(nv * s_lab[j4 + 0], nv * s_lab[j4 + 1],
                                   nv * s_lab[j4 + 2], nv * s_lab[j4 + 3]);
            *reinterpret_cast<float4*>(target_out + (long)(a0 + al) * BS + j4) = v;
        }
    }
}

extern "C" void kernel_launch(void* const* d_in, const int* in_sizes, int n_in,
                              void* d_out, int out_size) {
    const float* pd_scores = (const float*)d_in[0];
    const float* pd_bboxes = (const float*)d_in[1];
    const int*   gt_labels = (const int*)d_in[2];
    const float* gt_bboxes = (const float*)d_in[3];

    float* target = (float*)d_out;                       // (NA, BS)
    float* mask   = (float*)d_out + (size_t)NA * BS;     // (BS, NA)

    taa_fused<<<BS, NTH>>>(pd_scores, pd_bboxes, gt_labels, gt_bboxes,
                           target, mask);
}